// round 1
// baseline (speedup 1.0000x reference)
#include <cuda_runtime.h>

#define B_ 16
#define L_ 2048
#define E_ 256
#define SPLITS 16
#define CHUNK (L_ / SPLITS)   // 128 rows per block

// ---- scratch (no allocation allowed) ----
__device__ float g_X[B_ * E_];   // per-batch sum of valid x rows
__device__ float g_t[B_ * E_];   // Wk^T s
__device__ float g_c[B_];        // s . bk
__device__ float g_y[B_ * E_];   // sum_l w_l * x_l
__device__ float g_W[B_];        // sum_l w_l

// ---------------------------------------------------------------- zero
__global__ void k_zero() {
    int b = blockIdx.x, t = threadIdx.x;
    g_X[b * E_ + t] = 0.f;
    g_y[b * E_ + t] = 0.f;
    if (t == 0) g_W[b] = 0.f;
}

// ---------------------------------------------------------------- pass 1: X[b] = sum_{l<len} x[b,l]
__global__ void k_sumx(const float* __restrict__ x, const int* __restrict__ lengths) {
    int b = blockIdx.y;
    int start = blockIdx.x * CHUNK;
    int len = lengths[b];
    int end = min(start + CHUNK, len);
    int t = threadIdx.x;
    if (end <= start) return;
    float acc = 0.f;
    const float* xb = x + ((size_t)b * L_ + start) * E_ + t;
    for (int l = start; l < end; ++l, xb += E_)
        acc += *xb;
    atomicAdd(&g_X[b * E_ + t], acc);
}

// ---------------------------------------------------------------- s, t, c (tiny per-batch matvecs)
__global__ void k_stc(const float* __restrict__ Wq, const float* __restrict__ bq,
                      const float* __restrict__ Wk, const float* __restrict__ bk,
                      const int* __restrict__ lengths) {
    __shared__ float sX[E_];
    __shared__ float sS[E_];
    int b = blockIdx.x, t = threadIdx.x;
    sX[t] = g_X[b * E_ + t];
    __syncthreads();

    // s[f] = Wq row f . X + len * bq[f]
    float acc = 0.f;
    const float4* wq4 = (const float4*)(Wq + (size_t)t * E_);
    const float4* x4  = (const float4*)sX;
#pragma unroll 8
    for (int i = 0; i < E_ / 4; ++i) {
        float4 w = wq4[i], v = x4[i];
        acc += w.x * v.x + w.y * v.y + w.z * v.z + w.w * v.w;
    }
    int len = lengths[b];
    sS[t] = acc + (float)len * bq[t];
    __syncthreads();

    // t[e] = sum_f s[f] * Wk[f,e]   (coalesced across threads)
    float tv = 0.f;
#pragma unroll 8
    for (int f = 0; f < E_; ++f)
        tv += sS[f] * Wk[(size_t)f * E_ + t];
    g_t[b * E_ + t] = tv;

    // c = s . bk  (block tree reduce, reuse sX)
    sX[t] = sS[t] * bk[t];
    __syncthreads();
    for (int s = E_ / 2; s > 0; s >>= 1) {
        if (t < s) sX[t] += sX[t + s];
        __syncthreads();
    }
    if (t == 0) g_c[b] = sX[0];
}

// ---------------------------------------------------------------- pass 2: w_l = t.x_l + c ; y += w_l x_l ; W += w_l
__global__ void k_pass2(const float* __restrict__ x, const int* __restrict__ lengths) {
    int b = blockIdx.y;
    int start = blockIdx.x * CHUNK;
    int len = lengths[b];
    int end = min(start + CHUNK, len);
    int tid = threadIdx.x;
    int warp = tid >> 5, lane = tid & 31;

    __shared__ float ys[E_];
    __shared__ float wsh;
    ys[tid] = 0.f;
    if (tid == 0) wsh = 0.f;
    __syncthreads();

    if (end > start) {
        const float4* t4 = (const float4*)(g_t + b * E_);
        float4 ta = t4[lane];         // elems 4*lane .. 4*lane+3
        float4 tb = t4[32 + lane];    // elems 128+4*lane ..
        float c = g_c[b];

        float4 ya = make_float4(0.f, 0.f, 0.f, 0.f);
        float4 yb = make_float4(0.f, 0.f, 0.f, 0.f);
        float wacc = 0.f;

        // warp w handles rows start+warp, start+warp+8, ...
        for (int l = start + warp; l < end; l += 8) {
            const float4* xr = (const float4*)(x + ((size_t)b * L_ + l) * E_);
            float4 va = xr[lane];
            float4 vb = xr[32 + lane];
            float p = va.x * ta.x + va.y * ta.y + va.z * ta.z + va.w * ta.w
                    + vb.x * tb.x + vb.y * tb.y + vb.z * tb.z + vb.w * tb.w;
#pragma unroll
            for (int off = 16; off > 0; off >>= 1)
                p += __shfl_xor_sync(0xffffffffu, p, off);
            float w = p + c;
            ya.x += w * va.x; ya.y += w * va.y; ya.z += w * va.z; ya.w += w * va.w;
            yb.x += w * vb.x; yb.y += w * vb.y; yb.z += w * vb.z; yb.w += w * vb.w;
            if (lane == 0) wacc += w;
        }

        int e0 = 4 * lane;
        atomicAdd(&ys[e0 + 0], ya.x); atomicAdd(&ys[e0 + 1], ya.y);
        atomicAdd(&ys[e0 + 2], ya.z); atomicAdd(&ys[e0 + 3], ya.w);
        atomicAdd(&ys[128 + e0 + 0], yb.x); atomicAdd(&ys[128 + e0 + 1], yb.y);
        atomicAdd(&ys[128 + e0 + 2], yb.z); atomicAdd(&ys[128 + e0 + 3], yb.w);
        if (lane == 0) atomicAdd(&wsh, wacc);
    }
    __syncthreads();
    atomicAdd(&g_y[b * E_ + tid], ys[tid]);
    if (tid == 0) atomicAdd(&g_W[b], wsh);
}

// ---------------------------------------------------------------- final: out[b] = (Wv y + W*bv) / L
__global__ void k_final(const float* __restrict__ Wv, const float* __restrict__ bv,
                        float* __restrict__ out) {
    __shared__ float ys[E_];
    int b = blockIdx.x, t = threadIdx.x;
    ys[t] = g_y[b * E_ + t];
    __syncthreads();
    float acc = 0.f;
    const float4* wv4 = (const float4*)(Wv + (size_t)t * E_);
    const float4* y4  = (const float4*)ys;
#pragma unroll 8
    for (int i = 0; i < E_ / 4; ++i) {
        float4 w = wv4[i], v = y4[i];
        acc += w.x * v.x + w.y * v.y + w.z * v.z + w.w * v.w;
    }
    out[b * E_ + t] = (acc + g_W[b] * bv[t]) * (1.0f / (float)L_);
}

extern "C" void kernel_launch(void* const* d_in, const int* in_sizes, int n_in,
                              void* d_out, int out_size) {
    const float* x       = (const float*)d_in[0];
    const int*   lengths = (const int*)d_in[1];
    const float* Wq      = (const float*)d_in[2];
    const float* bq      = (const float*)d_in[3];
    const float* Wk      = (const float*)d_in[4];
    const float* bk      = (const float*)d_in[5];
    const float* Wv      = (const float*)d_in[6];
    const float* bv      = (const float*)d_in[7];
    float* out = (float*)d_out;

    k_zero<<<B_, E_>>>();
    k_sumx<<<dim3(SPLITS, B_), E_>>>(x, lengths);
    k_stc<<<B_, E_>>>(Wq, bq, Wk, bk, lengths);
    k_pass2<<<dim3(SPLITS, B_), E_>>>(x, lengths);
    k_final<<<B_, E_>>>(Wv, bv, out);
}